// round 3
// baseline (speedup 1.0000x reference)
#include <cuda_runtime.h>

#define B_ 2048
#define E_ 256
#define H_ 1024
#define V_ 42
#define S_ 100

#define BM 128
#define BN 32
#define BK 16

// ---------------- persistent device state (no allocations allowed) ----------
__device__ float g_x[B_ * V_];          // softmax output fed back as input
__device__ float g_h0[2][B_ * H_];      // ping-pong hidden layer 0
__device__ float g_h1[2][B_ * H_];      // ping-pong hidden layer 1
__device__ float g_c0[B_ * H_];
__device__ float g_c1[B_ * H_];

// ---------------- fast-but-accurate activations ----------------------------
// __expf -> MUFU.EX2 path, ~2^-21 rel err. tanh built from exp (abs err ~1e-7),
// deliberately NOT tanh.approx (~5e-4) to keep 100-step recurrence error low.
__device__ __forceinline__ float fsigm(float x) {
    return __fdividef(1.f, 1.f + __expf(-x));
}
__device__ __forceinline__ float ftanh(float x) {
    return __fdividef(2.f, 1.f + __expf(-2.f * x)) - 1.f;
}

// ---------------- init: zero state, one-hot start token --------------------
__global__ void init_kernel() {
    int idx = blockIdx.x * blockDim.x + threadIdx.x;
    if (idx < B_ * H_) {
        g_c0[idx] = 0.f;
        g_c1[idx] = 0.f;
        g_h1[0][idx] = 0.f;
    }
    if (idx < B_ * V_) {
        g_x[idx] = ((idx % V_) == V_ - 1) ? 1.f : 0.f;
    }
}

// ---------------- fc1: h0 = latent @ fc1_w^T + b  [2048,256]x[1024,256] ----
__global__ __launch_bounds__(256) void fc1_kernel(
    const float* __restrict__ latent,
    const float* __restrict__ w,
    const float* __restrict__ bias)
{
    __shared__ float As[16][68];
    __shared__ float Ws[16][68];
    const int tid = threadIdx.x;
    const int bm = blockIdx.y * 64, bn = blockIdx.x * 64;
    const int r = tid >> 2, kq = (tid & 3) * 4;
    const int tx = tid & 15, ty = tid >> 4;

    float acc[4][4];
#pragma unroll
    for (int i = 0; i < 4; i++)
#pragma unroll
        for (int j = 0; j < 4; j++) acc[i][j] = 0.f;

    for (int k0 = 0; k0 < E_; k0 += 16) {
        float4 av = *reinterpret_cast<const float4*>(latent + (size_t)(bm + r) * E_ + k0 + kq);
        float4 wv = *reinterpret_cast<const float4*>(w + (size_t)(bn + r) * E_ + k0 + kq);
        __syncthreads();
        As[kq + 0][r] = av.x; As[kq + 1][r] = av.y; As[kq + 2][r] = av.z; As[kq + 3][r] = av.w;
        Ws[kq + 0][r] = wv.x; Ws[kq + 1][r] = wv.y; Ws[kq + 2][r] = wv.z; Ws[kq + 3][r] = wv.w;
        __syncthreads();
#pragma unroll
        for (int kk = 0; kk < 16; kk++) {
            float4 a = *(const float4*)&As[kk][ty * 4];
            float4 b = *(const float4*)&Ws[kk][tx * 4];
            float am[4] = {a.x, a.y, a.z, a.w};
            float bn2[4] = {b.x, b.y, b.z, b.w};
#pragma unroll
            for (int mi = 0; mi < 4; mi++)
#pragma unroll
                for (int ni = 0; ni < 4; ni++)
                    acc[mi][ni] = fmaf(am[mi], bn2[ni], acc[mi][ni]);
        }
    }
    float bv[4];
#pragma unroll
    for (int ni = 0; ni < 4; ni++) bv[ni] = bias[bn + tx * 4 + ni];
#pragma unroll
    for (int mi = 0; mi < 4; mi++) {
        int m = bm + ty * 4 + mi;
#pragma unroll
        for (int ni = 0; ni < 4; ni++)
            g_h0[0][(size_t)m * H_ + bn + tx * 4 + ni] = acc[mi][ni] + bv[ni];
    }
}

// ---------------- fused gates GEMM + LSTM cell ------------------------------
// gates = A1 @ W1^T + A2 @ W2^T  (K-concat loop), then cell math in epilogue.
// Output tile: BM batch rows x BN hidden cols, with all 4 gates per element
// held by the same thread (cols {n, n+H, n+2H, n+3H} of the 4H gate space).
template <int K2, int LAYER>
__global__ __launch_bounds__(256, 2) void gates_kernel(
    int p,
    const float* __restrict__ W1,   // w_hh [4H, H]   (pairs with A1 = h_prev)
    const float* __restrict__ W2,   // w_ih [4H, K2]  (pairs with A2 = input)
    const float* __restrict__ bih,
    const float* __restrict__ bhh)
{
    const float* A1;
    const float* A2;
    float* cbuf;
    float* hout;
    if (LAYER == 0) {
        A1 = g_h0[p];     A2 = g_x;          cbuf = g_c0; hout = g_h0[p ^ 1];
    } else {
        A1 = g_h1[p];     A2 = g_h0[p ^ 1];  cbuf = g_c1; hout = g_h1[p ^ 1];
    }

    __shared__ float As[2][BK][BM + 4];        // [k][m], padded
    __shared__ float Ws[2][BK][4 * BN + 4];    // [k][g*32+n], padded

    const int tid = threadIdx.x;
    const int bm = blockIdx.y * BM;
    const int bn = blockIdx.x * BN;
    const int lr = tid >> 2;            // 0..63
    const int kq = (tid & 3) * 4;       // 0,4,8,12
    const int tx = tid & 15, ty = tid >> 4;

    float acc[8][8];                    // [mi][g*2+ni]
#pragma unroll
    for (int i = 0; i < 8; i++)
#pragma unroll
        for (int j = 0; j < 8; j++) acc[i][j] = 0.f;

    const int T1 = H_ / BK;
    const int T2 = (K2 + BK - 1) / BK;
    const int T = T1 + T2;

    float ra[8], rw[8];

    auto fetch = [&](int t) {
        const float* A; const float* W; int K; int kb;
        if (t < T1) { A = A1; W = W1; K = H_; kb = t * BK; }
        else        { A = A2; W = W2; K = K2; kb = (t - T1) * BK; }
#pragma unroll
        for (int rr = 0; rr < 2; rr++) {
            const int m = bm + rr * 64 + lr;
            const int c = rr * 64 + lr;
            const int wrow = (c >> 5) * H_ + bn + (c & 31);
            const float* Ap = A + (size_t)m * K + kb + kq;
            const float* Wp = W + (size_t)wrow * K + kb + kq;
            if ((K & 15) == 0) {        // compile-time for both phases
                float4 a4 = *reinterpret_cast<const float4*>(Ap);
                float4 w4 = *reinterpret_cast<const float4*>(Wp);
                ra[rr * 4 + 0] = a4.x; ra[rr * 4 + 1] = a4.y;
                ra[rr * 4 + 2] = a4.z; ra[rr * 4 + 3] = a4.w;
                rw[rr * 4 + 0] = w4.x; rw[rr * 4 + 1] = w4.y;
                rw[rr * 4 + 2] = w4.z; rw[rr * 4 + 3] = w4.w;
            } else {                    // K2 = 42 tail, strictly guarded (OOB!)
#pragma unroll
                for (int j = 0; j < 4; j++) {
                    int k = kb + kq + j;
                    float av = 0.f, wv = 0.f;
                    if (k < K) { av = Ap[j]; wv = Wp[j]; }
                    ra[rr * 4 + j] = av; rw[rr * 4 + j] = wv;
                }
            }
        }
    };
    auto sts = [&](int buf) {
#pragma unroll
        for (int rr = 0; rr < 2; rr++)
#pragma unroll
            for (int j = 0; j < 4; j++) {
                As[buf][kq + j][rr * 64 + lr] = ra[rr * 4 + j];
                Ws[buf][kq + j][rr * 64 + lr] = rw[rr * 4 + j];
            }
    };

    fetch(0);
    sts(0);
    __syncthreads();

    for (int t = 0; t < T; ++t) {
        const int cur = t & 1;
        if (t + 1 < T) fetch(t + 1);
#pragma unroll
        for (int kk = 0; kk < BK; ++kk) {
            float a[8], w[8];
            float4 a0 = *(const float4*)&As[cur][kk][ty * 8];
            float4 a1 = *(const float4*)&As[cur][kk][ty * 8 + 4];
            a[0] = a0.x; a[1] = a0.y; a[2] = a0.z; a[3] = a0.w;
            a[4] = a1.x; a[5] = a1.y; a[6] = a1.z; a[7] = a1.w;
#pragma unroll
            for (int g = 0; g < 4; g++) {
                float2 wv = *(const float2*)&Ws[cur][kk][g * BN + tx * 2];
                w[2 * g] = wv.x; w[2 * g + 1] = wv.y;
            }
#pragma unroll
            for (int mi = 0; mi < 8; mi++)
#pragma unroll
                for (int j = 0; j < 8; j++)
                    acc[mi][j] = fmaf(a[mi], w[j], acc[mi][j]);
        }
        if (t + 1 < T) sts(cur ^ 1);
        __syncthreads();
    }

    // ---- fused LSTM cell epilogue (torch gate order i,f,g,o) ----
    float bias[4][2];
#pragma unroll
    for (int g = 0; g < 4; g++)
#pragma unroll
        for (int ni = 0; ni < 2; ni++) {
            int col = g * H_ + bn + tx * 2 + ni;
            bias[g][ni] = bih[col] + bhh[col];
        }
#pragma unroll
    for (int mi = 0; mi < 8; mi++) {
        const int m = bm + ty * 8 + mi;
        const size_t off = (size_t)m * H_ + bn + tx * 2;
        float2 cold = *(const float2*)&cbuf[off];
        float2 cnv, hv;
        {
            float iv = acc[mi][0] + bias[0][0];
            float fv = acc[mi][2] + bias[1][0];
            float gv = acc[mi][4] + bias[2][0];
            float ov = acc[mi][6] + bias[3][0];
            float cn = fsigm(fv) * cold.x + fsigm(iv) * ftanh(gv);
            cnv.x = cn;
            hv.x = fsigm(ov) * ftanh(cn);
        }
        {
            float iv = acc[mi][1] + bias[0][1];
            float fv = acc[mi][3] + bias[1][1];
            float gv = acc[mi][5] + bias[2][1];
            float ov = acc[mi][7] + bias[3][1];
            float cn = fsigm(fv) * cold.y + fsigm(iv) * ftanh(gv);
            cnv.y = cn;
            hv.y = fsigm(ov) * ftanh(cn);
        }
        *(float2*)&cbuf[off] = cnv;
        *(float2*)&hout[off] = hv;
    }
}

// ---------------- logits + softmax feedback --------------------------------
#define LB 16
#define KC 64
__global__ __launch_bounds__(256) void logits_kernel(
    int p, int t,
    const float* __restrict__ w,     // fc2_w [V, H]
    const float* __restrict__ bias,  // fc2_b [V]
    float* __restrict__ out)         // [B, S, V]
{
    const float* h = g_h1[p ^ 1];
    __shared__ float hs[LB][KC + 1];
    __shared__ float ws[KC][48];
    __shared__ float ls[LB][48];
    const int tid = threadIdx.x;
    const int b0 = blockIdx.x * LB;
    const int r = tid >> 4, q = tid & 15;

    float acc0 = 0.f, acc1 = 0.f, acc2 = 0.f;
    for (int k0 = 0; k0 < H_; k0 += KC) {
        __syncthreads();
#pragma unroll
        for (int i = 0; i < 4; i++) {
            int idx = tid + i * 256;
            int rr = idx >> 6, kk = idx & 63;
            hs[rr][kk] = h[(size_t)(b0 + rr) * H_ + k0 + kk];
        }
        for (int idx = tid; idx < KC * V_; idx += 256) {
            int kk = idx / V_, v = idx - kk * V_;
            ws[kk][v] = w[(size_t)v * H_ + k0 + kk];
        }
        for (int idx = tid; idx < KC * (48 - V_); idx += 256) {
            int kk = idx / (48 - V_);
            ws[kk][V_ + idx % (48 - V_)] = 0.f;
        }
        __syncthreads();
#pragma unroll
        for (int kk = 0; kk < KC; kk++) {
            float a = hs[r][kk];
            acc0 = fmaf(a, ws[kk][q], acc0);
            acc1 = fmaf(a, ws[kk][q + 16], acc1);
            acc2 = fmaf(a, ws[kk][q + 32], acc2);   // pad cols are 0
        }
    }
    const int b = b0 + r;
    const size_t ob = (size_t)b * S_ * V_ + (size_t)t * V_;
    float l0 = acc0 + bias[q];
    float l1 = acc1 + bias[q + 16];
    ls[r][q] = l0;      out[ob + q] = l0;
    ls[r][q + 16] = l1; out[ob + q + 16] = l1;
    if (q + 32 < V_) {
        float l2 = acc2 + bias[q + 32];
        ls[r][q + 32] = l2;
        out[ob + q + 32] = l2;
    }
    __syncthreads();
    if (tid < LB) {
        float mx = -1e30f;
#pragma unroll
        for (int v = 0; v < V_; v++) mx = fmaxf(mx, ls[tid][v]);
        float ev[V_];
        float sum = 0.f;
#pragma unroll
        for (int v = 0; v < V_; v++) {
            ev[v] = __expf(ls[tid][v] - mx);
            sum += ev[v];
        }
        float inv = __fdividef(1.f, sum);
        const int bb = b0 + tid;
#pragma unroll
        for (int v = 0; v < V_; v++) g_x[(size_t)bb * V_ + v] = ev[v] * inv;
    }
}

// ---------------- driver ----------------------------------------------------
extern "C" void kernel_launch(void* const* d_in, const int* in_sizes, int n_in,
                              void* d_out, int out_size)
{
    const float* latent = (const float*)d_in[0];
    const float* fc1_w  = (const float*)d_in[1];
    const float* fc1_b  = (const float*)d_in[2];
    const float* fc2_w  = (const float*)d_in[3];
    const float* fc2_b  = (const float*)d_in[4];
    const float* w_ih0  = (const float*)d_in[5];
    const float* w_hh0  = (const float*)d_in[6];
    const float* b_ih0  = (const float*)d_in[7];
    const float* b_hh0  = (const float*)d_in[8];
    const float* w_ih1  = (const float*)d_in[9];
    const float* w_hh1  = (const float*)d_in[10];
    const float* b_ih1  = (const float*)d_in[11];
    const float* b_hh1  = (const float*)d_in[12];
    float* out = (float*)d_out;

    init_kernel<<<(B_ * H_ + 255) / 256, 256>>>();
    fc1_kernel<<<dim3(H_ / 64, B_ / 64), 256>>>(latent, fc1_w, fc1_b);

    for (int t = 0; t < S_; ++t) {
        const int p = t & 1;
        gates_kernel<V_, 0><<<dim3(H_ / BN, B_ / BM), 256>>>(p, w_hh0, w_ih0, b_ih0, b_hh0);
        gates_kernel<H_, 1><<<dim3(H_ / BN, B_ / BM), 256>>>(p, w_hh1, w_ih1, b_ih1, b_hh1);
        logits_kernel<<<B_ / LB, 256>>>(p, t, fc2_w, fc2_b, out);
    }
}

// round 4
// speedup vs baseline: 1.8660x; 1.8660x over previous
#include <cuda_runtime.h>
#include <cstdint>

#define B_ 2048
#define E_ 256
#define H_ 1024
#define V_ 42
#define S_ 100
#define XP 48            // padded x width (V_ 42 -> 48) so all K-tiles are full

// ---------------- persistent device state (no allocations allowed) ----------
__device__ float g_x[B_ * XP];          // softmax output (tf32-rounded), padded
__device__ float g_h0[2][B_ * H_];      // ping-pong hidden layer 0 (tf32-rounded)
__device__ float g_h1[2][B_ * H_];      // ping-pong hidden layer 1 (tf32-rounded)
__device__ float g_c0[B_ * H_];         // cell state fp32
__device__ float g_c1[B_ * H_];
// rna-rounded tf32 weights (rounded once per run; raw-bit truncation is biased!)
__device__ float g_whh0t[4 * H_ * H_];
__device__ float g_wih0t[4 * H_ * XP];  // zero-padded cols 42..47
__device__ float g_whh1t[4 * H_ * H_];
__device__ float g_wih1t[4 * H_ * H_];

// ---------------- helpers ---------------------------------------------------
__device__ __forceinline__ float rnd_tf32(float x) {
    uint32_t u;
    asm("cvt.rna.tf32.f32 %0, %1;" : "=r"(u) : "f"(x));
    return __uint_as_float(u);
}
__device__ __forceinline__ float fsigm(float x) {
    return __fdividef(1.f, 1.f + __expf(-x));
}
__device__ __forceinline__ float ftanh(float x) {
    return __fdividef(2.f, 1.f + __expf(-2.f * x)) - 1.f;
}

// ---------------- weight prep: pad + rna-round to tf32 ----------------------
__global__ void prep_kernel(const float* __restrict__ src, float* __restrict__ dst,
                            int srcK, int dstK, int total) {
    int i = blockIdx.x * blockDim.x + threadIdx.x;
    if (i >= total) return;
    int r = i / dstK, k = i - r * dstK;
    float v = (k < srcK) ? src[(size_t)r * srcK + k] : 0.f;
    dst[i] = rnd_tf32(v);
}

// ---------------- init: zero state, one-hot start token ---------------------
__global__ void init_kernel() {
    int idx = blockIdx.x * blockDim.x + threadIdx.x;
    if (idx < B_ * H_) {
        g_c0[idx] = 0.f;
        g_c1[idx] = 0.f;
        g_h1[0][idx] = 0.f;
    }
    if (idx < B_ * XP) {
        g_x[idx] = ((idx % XP) == V_ - 1) ? 1.f : 0.f;
    }
}

// ---------------- fc1: h0 = latent @ fc1_w^T + b (one-time, fp32) -----------
__global__ __launch_bounds__(256) void fc1_kernel(
    const float* __restrict__ latent,
    const float* __restrict__ w,
    const float* __restrict__ bias)
{
    __shared__ float As[16][68];
    __shared__ float Ws[16][68];
    const int tid = threadIdx.x;
    const int bm = blockIdx.y * 64, bn = blockIdx.x * 64;
    const int r = tid >> 2, kq = (tid & 3) * 4;
    const int tx = tid & 15, ty = tid >> 4;

    float acc[4][4];
#pragma unroll
    for (int i = 0; i < 4; i++)
#pragma unroll
        for (int j = 0; j < 4; j++) acc[i][j] = 0.f;

    for (int k0 = 0; k0 < E_; k0 += 16) {
        float4 av = *reinterpret_cast<const float4*>(latent + (size_t)(bm + r) * E_ + k0 + kq);
        float4 wv = *reinterpret_cast<const float4*>(w + (size_t)(bn + r) * E_ + k0 + kq);
        __syncthreads();
        As[kq + 0][r] = av.x; As[kq + 1][r] = av.y; As[kq + 2][r] = av.z; As[kq + 3][r] = av.w;
        Ws[kq + 0][r] = wv.x; Ws[kq + 1][r] = wv.y; Ws[kq + 2][r] = wv.z; Ws[kq + 3][r] = wv.w;
        __syncthreads();
#pragma unroll
        for (int kk = 0; kk < 16; kk++) {
            float4 a = *(const float4*)&As[kk][ty * 4];
            float4 b = *(const float4*)&Ws[kk][tx * 4];
            float am[4] = {a.x, a.y, a.z, a.w};
            float bn2[4] = {b.x, b.y, b.z, b.w};
#pragma unroll
            for (int mi = 0; mi < 4; mi++)
#pragma unroll
                for (int ni = 0; ni < 4; ni++)
                    acc[mi][ni] = fmaf(am[mi], bn2[ni], acc[mi][ni]);
        }
    }
    float bv[4];
#pragma unroll
    for (int ni = 0; ni < 4; ni++) bv[ni] = bias[bn + tx * 4 + ni];
#pragma unroll
    for (int mi = 0; mi < 4; mi++) {
        int m = bm + ty * 4 + mi;
#pragma unroll
        for (int ni = 0; ni < 4; ni++)
            g_h0[0][(size_t)m * H_ + bn + tx * 4 + ni] = rnd_tf32(acc[mi][ni] + bv[ni]);
    }
}

// ---------------- TF32 tensor-core gates GEMM + fused LSTM cell --------------
// gates = h_prev @ W1^T + x_in @ W2^T  (K-concat), via mma.sync m16n8k8 tf32.
// CTA tile: 128 batch rows x 128 "j" cols, j = nl*4 + g (gate-interleaved) so
// the 4 gates of one hidden col live in one lane pair -> shfl.xor epilogue.
template <int K2P, int LAYER>
__global__ __launch_bounds__(256, 2) void gates_mma(
    int p,
    const float* __restrict__ W1,    // prepped w_hh [4H, 1024]
    const float* __restrict__ W2,    // prepped w_ih [4H, K2P]
    const float* __restrict__ bih,
    const float* __restrict__ bhh)
{
    constexpr int T1 = H_ / 16;          // 64 tiles from the hh part
    constexpr int T2 = K2P / 16;         // ih part (K2P is padded, always full)
    constexpr int T = T1 + T2;

    const float* A1;
    const float* A2;
    float* cbuf;
    float* hout;
    if (LAYER == 0) { A1 = g_h0[p]; A2 = g_x;          cbuf = g_c0; hout = g_h0[p ^ 1]; }
    else            { A1 = g_h1[p]; A2 = g_h0[p ^ 1];  cbuf = g_c1; hout = g_h1[p ^ 1]; }
    const int strideA2 = (LAYER == 0) ? XP : H_;

    __shared__ float As[2][128][20];     // [stage][m][k], stride 20 -> conflict-free frags
    __shared__ float Bs[2][128][20];     // [stage][j][k]

    const int tid = threadIdx.x;
    const int bm = blockIdx.y * 128;
    const int bn = blockIdx.x * 32;

    // ---- loader mapping: 2 threads per row, 2x 16B cp.async each ----
    const int lrow = tid >> 1;           // 0..127
    const int lkq = (tid & 1) * 8;       // 0 or 8
    const int wrow = (lrow & 3) * H_ + bn + (lrow >> 2);   // j = nl*4+g -> W row
    const float* aRow1 = A1 + (size_t)(bm + lrow) * H_;
    const float* aRow2 = A2 + (size_t)(bm + lrow) * strideA2;
    const float* bRow1 = W1 + (size_t)wrow * H_;
    const float* bRow2 = W2 + (size_t)wrow * K2P;

    auto issue = [&](int kt, int buf) {
        const float* as;
        const float* bs;
        if (kt < T1) { int k = kt * 16 + lkq;        as = aRow1 + k; bs = bRow1 + k; }
        else         { int k = (kt - T1) * 16 + lkq; as = aRow2 + k; bs = bRow2 + k; }
        uint32_t da = (uint32_t)__cvta_generic_to_shared(&As[buf][lrow][lkq]);
        uint32_t db = (uint32_t)__cvta_generic_to_shared(&Bs[buf][lrow][lkq]);
        asm volatile(
            "cp.async.ca.shared.global [%0], [%1], 16;\n\t"
            "cp.async.ca.shared.global [%2], [%3], 16;\n\t"
            "cp.async.ca.shared.global [%4], [%5], 16;\n\t"
            "cp.async.ca.shared.global [%6], [%7], 16;\n\t"
            :: "r"(da), "l"(as), "r"(da + 16), "l"(as + 4),
               "r"(db), "l"(bs), "r"(db + 16), "l"(bs + 4)
            : "memory");
    };

    // ---- mma mapping ----
    const int lane = tid & 31;
    const int wid = tid >> 5;
    const int wm = wid & 1;              // 2 warps over m (64 rows each)
    const int wj = wid >> 1;             // 4 warps over j (32 cols each)
    const int gid = lane >> 2, tig = lane & 3;

    float acc[4][4][4];
#pragma unroll
    for (int a = 0; a < 4; a++)
#pragma unroll
        for (int b = 0; b < 4; b++)
#pragma unroll
            for (int c = 0; c < 4; c++) acc[a][b][c] = 0.f;

    issue(0, 0);
    asm volatile("cp.async.commit_group;" ::: "memory");

    for (int kt = 0; kt < T; ++kt) {
        const int buf = kt & 1;
        if (kt + 1 < T) {
            issue(kt + 1, buf ^ 1);
            asm volatile("cp.async.commit_group;" ::: "memory");
            asm volatile("cp.async.wait_group 1;" ::: "memory");
        } else {
            asm volatile("cp.async.wait_group 0;" ::: "memory");
        }
        __syncthreads();
#pragma unroll
        for (int h8 = 0; h8 < 2; h8++) {
            const int ko = h8 * 8 + tig;
            uint32_t a[4][4], b[4][2];
#pragma unroll
            for (int mt = 0; mt < 4; mt++) {
                const int m0 = wm * 64 + mt * 16 + gid;
                a[mt][0] = __float_as_uint(As[buf][m0][ko]);
                a[mt][1] = __float_as_uint(As[buf][m0 + 8][ko]);
                a[mt][2] = __float_as_uint(As[buf][m0][ko + 4]);
                a[mt][3] = __float_as_uint(As[buf][m0 + 8][ko + 4]);
            }
#pragma unroll
            for (int nt = 0; nt < 4; nt++) {
                const int j0 = wj * 32 + nt * 8 + gid;
                b[nt][0] = __float_as_uint(Bs[buf][j0][ko]);
                b[nt][1] = __float_as_uint(Bs[buf][j0][ko + 4]);
            }
#pragma unroll
            for (int mt = 0; mt < 4; mt++)
#pragma unroll
                for (int nt = 0; nt < 4; nt++)
                    asm volatile(
                        "mma.sync.aligned.m16n8k8.row.col.f32.tf32.tf32.f32 "
                        "{%0,%1,%2,%3}, {%4,%5,%6,%7}, {%8,%9}, {%0,%1,%2,%3};"
                        : "+f"(acc[mt][nt][0]), "+f"(acc[mt][nt][1]),
                          "+f"(acc[mt][nt][2]), "+f"(acc[mt][nt][3])
                        : "r"(a[mt][0]), "r"(a[mt][1]), "r"(a[mt][2]), "r"(a[mt][3]),
                          "r"(b[nt][0]), "r"(b[nt][1]));
        }
        __syncthreads();
    }

    // ---- fused LSTM cell epilogue via lane-pair shuffle ----
    // tig even lanes ("A") hold (i_pre, f_pre); odd ("B") hold (g_pre, o_pre)
    const bool isA = (tig & 1) == 0;
    const int gl = (tig & 1) * 2;
#pragma unroll
    for (int nt = 0; nt < 4; nt++) {
        const int col = bn + wj * 8 + nt * 2 + (tig >> 1);
        const float bias0 = bih[gl * H_ + col] + bhh[gl * H_ + col];
        const float bias1 = bih[(gl + 1) * H_ + col] + bhh[(gl + 1) * H_ + col];
#pragma unroll
        for (int mt = 0; mt < 4; mt++) {
#pragma unroll
            for (int rh = 0; rh < 2; rh++) {
                const int m = bm + wm * 64 + mt * 16 + gid + rh * 8;
                const size_t off = (size_t)m * H_ + col;
                const float p0 = acc[mt][nt][rh * 2 + 0] + bias0;  // A: i, B: g
                const float p1 = acc[mt][nt][rh * 2 + 1] + bias1;  // A: f, B: o
                const float e = __expf(isA ? -p0 : -2.f * p0);
                const float q0 = __fdividef(isA ? 1.f : 2.f, 1.f + e) - (isA ? 0.f : 1.f);
                const float q1 = fsigm(p1);                        // A: sig(f), B: sig(o)
                const float partner = __shfl_xor_sync(0xffffffffu, q0, 1); // A gets tanh(g)
                const float cold = isA ? cbuf[off] : 0.f;
                const float cn = fmaf(q1, cold, q0 * partner);     // A: sf*c + si*tg
                const float th = ftanh(cn);
                const float th2 = __shfl_xor_sync(0xffffffffu, th, 1);     // B gets tanh(c_new)
                if (isA) cbuf[off] = cn;
                else     hout[off] = rnd_tf32(q1 * th2);           // B: sig(o)*tanh(c_new)
            }
        }
    }
}

// ---------------- logits + softmax feedback ---------------------------------
#define LB 16
#define KC 64
__global__ __launch_bounds__(256) void logits_kernel(
    int p, int t,
    const float* __restrict__ w,     // fc2_w [V, H]
    const float* __restrict__ bias,  // fc2_b [V]
    float* __restrict__ out)         // [B, S, V]
{
    const float* h = g_h1[p ^ 1];
    __shared__ float hs[LB][KC + 1];
    __shared__ float ws[KC][48];
    __shared__ float ls[LB][48];
    const int tid = threadIdx.x;
    const int b0 = blockIdx.x * LB;
    const int r = tid >> 4, q = tid & 15;

    float acc0 = 0.f, acc1 = 0.f, acc2 = 0.f;
    for (int k0 = 0; k0 < H_; k0 += KC) {
        __syncthreads();
#pragma unroll
        for (int i = 0; i < 4; i++) {
            int idx = tid + i * 256;
            int rr = idx >> 6, kk = idx & 63;
            hs[rr][kk] = h[(size_t)(b0 + rr) * H_ + k0 + kk];
        }
        for (int idx = tid; idx < KC * V_; idx += 256) {
            int kk = idx / V_, v = idx - kk * V_;
            ws[kk][v] = w[(size_t)v * H_ + k0 + kk];
        }
        for (int idx = tid; idx < KC * (48 - V_); idx += 256) {
            int kk = idx / (48 - V_);
            ws[kk][V_ + idx % (48 - V_)] = 0.f;
        }
        __syncthreads();
#pragma unroll
        for (int kk = 0; kk < KC; kk++) {
            float a = hs[r][kk];
            acc0 = fmaf(a, ws[kk][q], acc0);
            acc1 = fmaf(a, ws[kk][q + 16], acc1);
            acc2 = fmaf(a, ws[kk][q + 32], acc2);   // pad cols are 0
        }
    }
    const int b = b0 + r;
    const size_t ob = (size_t)b * S_ * V_ + (size_t)t * V_;
    float l0 = acc0 + bias[q];
    float l1 = acc1 + bias[q + 16];
    ls[r][q] = l0;      out[ob + q] = l0;
    ls[r][q + 16] = l1; out[ob + q + 16] = l1;
    if (q + 32 < V_) {
        float l2 = acc2 + bias[q + 32];
        ls[r][q + 32] = l2;
        out[ob + q + 32] = l2;
    }
    __syncthreads();
    if (tid < LB) {
        float mx = -1e30f;
#pragma unroll
        for (int v = 0; v < V_; v++) mx = fmaxf(mx, ls[tid][v]);
        float ev[V_];
        float sum = 0.f;
#pragma unroll
        for (int v = 0; v < V_; v++) {
            ev[v] = __expf(ls[tid][v] - mx);
            sum += ev[v];
        }
        float inv = __fdividef(1.f, sum);
        const int bb = b0 + tid;
#pragma unroll
        for (int v = 0; v < V_; v++)
            g_x[(size_t)bb * XP + v] = rnd_tf32(ev[v] * inv);
    }
}

// ---------------- driver ----------------------------------------------------
extern "C" void kernel_launch(void* const* d_in, const int* in_sizes, int n_in,
                              void* d_out, int out_size)
{
    const float* latent = (const float*)d_in[0];
    const float* fc1_w  = (const float*)d_in[1];
    const float* fc1_b  = (const float*)d_in[2];
    const float* fc2_w  = (const float*)d_in[3];
    const float* fc2_b  = (const float*)d_in[4];
    const float* w_ih0  = (const float*)d_in[5];
    const float* w_hh0  = (const float*)d_in[6];
    const float* b_ih0  = (const float*)d_in[7];
    const float* b_hh0  = (const float*)d_in[8];
    const float* w_ih1  = (const float*)d_in[9];
    const float* w_hh1  = (const float*)d_in[10];
    const float* b_ih1  = (const float*)d_in[11];
    const float* b_hh1  = (const float*)d_in[12];
    float* out = (float*)d_out;

    // weight prep: rna-round to tf32 (+ pad w_ih0 to 48 cols)
    float* whh0t; cudaGetSymbolAddress((void**)&whh0t, g_whh0t);
    float* wih0t; cudaGetSymbolAddress((void**)&wih0t, g_wih0t);
    float* whh1t; cudaGetSymbolAddress((void**)&whh1t, g_whh1t);
    float* wih1t; cudaGetSymbolAddress((void**)&wih1t, g_wih1t);
    const int nHH = 4 * H_ * H_;
    const int nIH0 = 4 * H_ * XP;
    prep_kernel<<<(nHH + 255) / 256, 256>>>(w_hh0, whh0t, H_, H_, nHH);
    prep_kernel<<<(nIH0 + 255) / 256, 256>>>(w_ih0, wih0t, V_, XP, nIH0);
    prep_kernel<<<(nHH + 255) / 256, 256>>>(w_hh1, whh1t, H_, H_, nHH);
    prep_kernel<<<(nHH + 255) / 256, 256>>>(w_ih1, wih1t, H_, H_, nHH);

    init_kernel<<<(B_ * H_ + 255) / 256, 256>>>();
    fc1_kernel<<<dim3(H_ / 64, B_ / 64), 256>>>(latent, fc1_w, fc1_b);

    for (int t = 0; t < S_; ++t) {
        const int p = t & 1;
        gates_mma<XP, 0><<<dim3(H_ / 32, B_ / 128), 256>>>(p, whh0t, wih0t, b_ih0, b_hh0);
        gates_mma<H_, 1><<<dim3(H_ / 32, B_ / 128), 256>>>(p, whh1t, wih1t, b_ih1, b_hh1);
        logits_kernel<<<B_ / LB, 256>>>(p, t, fc2_w, fc2_b, out);
    }
}